// round 11
// baseline (speedup 1.0000x reference)
#include <cuda_runtime.h>
#include <cfloat>
#include <cstdint>
#include <cstring>

// Problem constants
#define NITEMS 2
#define CCH 64
#define HH 96
#define WW 96
#define HP 94
#define WP 94
#define MM (HP*WP)          // 8836 patches per item
#define SY 24               // patch rows per strip block
#define NSTRIP 4
#define NDY 187             // Dy in [-93, 93]
#define VST 98              // Vp plane row stride (floats)
#define XPAD 68             // padded floats per x-column (272B, 16B-aligned)
#define ROWP (WW*XPAD)      // 6528 floats per padded row slab [x][c]
#define ROWG (WW*CCH)       // 6144 floats per row slab in GMEM
#define NTHR 512

// Static device scratch (allocation-free rule)
__device__ float g_feat[2][NITEMS][HH][WW][CCH];          // normalized, [t][n][row][x][c]
__device__ unsigned long long g_best64[NITEMS][MM];       // packed (value, ~r)

__device__ __forceinline__ unsigned su(const void* p) {
    return (unsigned)__cvta_generic_to_shared(p);
}

__device__ __forceinline__ unsigned long long packkey(float v, int r) {
    unsigned u = __float_as_uint(v);
    u = (u & 0x80000000u) ? ~u : (u | 0x80000000u);   // monotone float -> uint
    return ((unsigned long long)u << 32) | (unsigned)(~r);  // bigger = better; tie -> smaller r
}

// ---------------------------------------------------------------------------
// Kernel 1: per-pixel channel L2 normalization, fp32 NCHW -> [row][x][c]
// ---------------------------------------------------------------------------
__global__ void normalize_kernel(const float* __restrict__ f1,
                                 const float* __restrict__ f2) {
    __shared__ float tile[CCH][WW + 1];
    __shared__ float scale[WW];
    int row = blockIdx.x, t = blockIdx.y, n = blockIdx.z;
    const float* src = (t == 0 ? f1 : f2) + (size_t)n * CCH * HH * WW + (size_t)row * WW;

    for (int j = threadIdx.x; j < CCH * WW; j += 256) {
        int c = j / WW, x = j % WW;
        tile[c][x] = src[(size_t)c * HH * WW + x];
    }
    __syncthreads();
    if (threadIdx.x < WW) {
        float ss = 0.f;
        #pragma unroll
        for (int c = 0; c < CCH; c++) { float v = tile[c][threadIdx.x]; ss += v * v; }
        scale[threadIdx.x] = 1.0f / fmaxf(sqrtf(ss), 1e-12f);
    }
    __syncthreads();
    float* dst = &g_feat[t][n][row][0][0];
    for (int j = threadIdx.x; j < CCH * WW; j += 256) {
        int x = j >> 6, c = j & 63;
        dst[x * CCH + c] = tile[c][x] * scale[x];
    }
}

// ---------------------------------------------------------------------------
// Kernel 2: reset argmax state (required every graph replay)
// ---------------------------------------------------------------------------
__global__ void init_kernel() {
    int i = blockIdx.x * 256 + threadIdx.x;
    if (i < NITEMS * MM) ((unsigned long long*)g_best64)[i] = 0ull;
}

// ---------------------------------------------------------------------------
// Kernel 3: displacement-decomposed correlation + argmax, 512 threads.
// c-packed f32x2 MACs: both FFMA2 operands straight from LDS.128, no dup movs.
// 2-D lane tiling (8 x-groups x 4 xr-groups), warp tile 24x24.
// Vertical running sums in registers; V plane in smem for the cross-thread
// horizontal 3-diagonal argmax.
// ---------------------------------------------------------------------------
__device__ __forceinline__ void load_rows(const float* fa, const float* fb,
                                          float* da, float* db, int tid) {
    // 1536 16B-chunks per tensor row slab (96 x * 16 c-chunks); pad x-stride
    // 64 -> 68 floats in smem. 3072 chunks total over 512 threads = 6 passes.
    #pragma unroll
    for (int q = 0; q < 6; q++) {
        int idx = tid + NTHR * q;          // 0..3071
        int tsel = idx >= 1536;
        int g = idx - 1536 * tsel;
        int x = g >> 4, cc = g & 15;
        const float* sp = (tsel ? fb : fa) + g * 4;
        float* dbase = tsel ? db : da;
        unsigned dp = su(dbase + x * XPAD + cc * 4);
        asm volatile("cp.async.cg.shared.global [%0], [%1], 16;\n" :: "r"(dp), "l"(sp));
    }
    asm volatile("cp.async.commit_group;\n" ::: "memory");
}

__global__ __launch_bounds__(NTHR, 1)
void corr_kernel() {
    extern __shared__ float sm[];
    float* smRows = sm;                    // 2 bufs x (A + B) = 4*ROWP
    float* Vp = sm + 4 * ROWP;             // 96*VST

    const int d = blockIdx.x >> 2;         // 0..186
    const int s = blockIdx.x & 3;
    const int Dy = d - 93;
    const int item = blockIdx.y;
    const int ylo = Dy < 0 ? -Dy : 0;
    const int yhi = HP - (Dy > 0 ? Dy : 0);
    const int y0 = ylo + s * SY;
    if (y0 >= yhi) return;
    int rows = yhi - y0; if (rows > SY) rows = SY;

    const int tid = threadIdx.x;
    const int lane = tid & 31;
    const int wrp = tid >> 5;              // 0..15
    const int wx = wrp & 3;                // warp grid 4x4
    const int wy = wrp >> 2;

    const float* finBase  = &g_feat[0][item][0][0][0];
    const float* frefBase = &g_feat[1][item][0][0][0];

    // ownership: x = wx*24 + (lane&7)*3 + i (i<3); xr = wy*24 + (lane>>3)*6 + j (j<6)
    const int ax  = wx * 24 + (lane & 7) * 3;
    const int bxr = wy * 24 + (lane >> 3) * 6;

    // register state: packed-c accumulators + scalar vertical running sums
    unsigned long long acc[3][6];
    float S1[3][6], S2[3][6];
    #pragma unroll
    for (int i = 0; i < 3; i++)
        #pragma unroll
        for (int j = 0; j < 6; j++) { S1[i][j] = 0.f; S2[i][j] = 0.f; }

    // prefetch row-pair k=0
    load_rows(finBase + (size_t)y0 * ROWG, frefBase + (size_t)(y0 + Dy) * ROWG,
              smRows, smRows + ROWP, tid);

    for (int k = 0; k < rows + 2; k++) {
        const int buf = k & 1;
        asm volatile("cp.async.wait_group 0;\n" ::: "memory");
        __syncthreads();
        if (k + 1 < rows + 2) {
            int p = y0 + k + 1;
            load_rows(finBase + (size_t)p * ROWG, frefBase + (size_t)(p + Dy) * ROWG,
                      smRows + (buf ^ 1) * 2 * ROWP, smRows + (buf ^ 1) * 2 * ROWP + ROWP, tid);
        }

        const float* aptr = smRows + buf * 2 * ROWP + ax * XPAD;
        const float* bptr = smRows + buf * 2 * ROWP + ROWP + bxr * XPAD;

        #pragma unroll
        for (int i = 0; i < 3; i++)
            #pragma unroll
            for (int j = 0; j < 6; j++) acc[i][j] = 0ull;

        // ---- rowdot GEMM: c-quads, all operands via LDS.128, no dups ----
        #pragma unroll 4
        for (int cq = 0; cq < 16; cq++) {
            ulonglong2 av[3];
            #pragma unroll
            for (int i = 0; i < 3; i++)
                av[i] = *(const ulonglong2*)(aptr + i * XPAD + cq * 4);
            #pragma unroll
            for (int j = 0; j < 6; j++) {
                ulonglong2 bv = *(const ulonglong2*)(bptr + j * XPAD + cq * 4);
                #pragma unroll
                for (int i = 0; i < 3; i++) {
                    asm("fma.rn.f32x2 %0, %1, %2, %0;" : "+l"(acc[i][j]) : "l"(av[i].x), "l"(bv.x));
                    asm("fma.rn.f32x2 %0, %1, %2, %0;" : "+l"(acc[i][j]) : "l"(av[i].y), "l"(bv.y));
                }
            }
        }

        // ---- fold c-halves, vertical running sums in regs, V -> smem ----
        const bool emit = (k >= 2);
        #pragma unroll
        for (int i = 0; i < 3; i++) {
            float* vpp = Vp + (ax + i) * VST + bxr;
            #pragma unroll
            for (int j = 0; j < 6; j++) {
                float2 h; memcpy(&h, &acc[i][j], 8);
                float rd = h.x + h.y;
                if (emit) vpp[j] = S2[i][j] + rd;
                S2[i][j] = S1[i][j] + rd;
                S1[i][j] = rd;
            }
        }

        // ---- horizontal 3-diag sum + argmax over rx, merged via atomicMax ----
        if (emit) {
            __syncthreads();
            const int y = y0 + k - 2;
            const int ry = y + Dy;
            #pragma unroll
            for (int i = 0; i < 6; i++) {
                int xx = wrp + 16 * i;
                float bv = -FLT_MAX; int brx = 0;
                if (xx < HP) {
                    const float* v0 = Vp + xx * VST;
                    const float* v1 = v0 + VST + 1;
                    const float* v2 = v1 + VST + 1;
                    #pragma unroll
                    for (int j = 0; j < 3; j++) {
                        int rx = lane + 32 * j;
                        if (rx < HP) {
                            float v = v0[rx] + v1[rx] + v2[rx];
                            if (v > bv) { bv = v; brx = rx; }
                        }
                    }
                }
                #pragma unroll
                for (int off = 16; off >= 1; off >>= 1) {
                    float ov = __shfl_down_sync(0xffffffffu, bv, off);
                    int orx = __shfl_down_sync(0xffffffffu, brx, off);
                    if (ov > bv || (ov == bv && orx < brx)) { bv = ov; brx = orx; }
                }
                if (lane == 0 && xx < HP) {
                    atomicMax(&g_best64[item][y * WP + xx], packkey(bv, ry * WP + brx));
                }
            }
        }
    }
}

// ---------------------------------------------------------------------------
// Kernel 4: decode best index -> flow -> shift -> reorder. out (N,18,H,W) f32
// ---------------------------------------------------------------------------
__global__ void epilogue_kernel(float* __restrict__ out) {
    int i = blockIdx.x * 256 + threadIdx.x;
    const int total = NITEMS * 18 * HH * WW;
    if (i >= total) return;
    int w = i % WW;
    int h = (i / WW) % HH;
    int ch = (i / (WW * HH)) % 18;
    int n = i / (WW * HH * 18);
    int s = ch >> 1, comp = ch & 1;
    int si = s / 3, sj = s % 3;
    int y = h - si, x = w - sj;
    float val = 0.f;
    if (y >= 0 && y < HP && x >= 0 && x < WP) {
        unsigned long long key = g_best64[n][y * WP + x];
        int idx = (int)(~(unsigned)(key & 0xffffffffull));
        val = (comp == 0) ? (float)(idx / WP - y) : (float)(idx % WP - x);
    }
    out[i] = val;
}

// ---------------------------------------------------------------------------
extern "C" void kernel_launch(void* const* d_in, const int* in_sizes, int n_in,
                              void* d_out, int out_size) {
    const float* f1 = (const float*)d_in[0];
    const float* f2 = (const float*)d_in[1];

    const int smem_bytes = (4 * ROWP + HH * VST) * (int)sizeof(float);  // ~142KB
    cudaFuncSetAttribute(corr_kernel,
                         cudaFuncAttributeMaxDynamicSharedMemorySize, smem_bytes);

    normalize_kernel<<<dim3(HH, 2, NITEMS), 256>>>(f1, f2);
    init_kernel<<<(NITEMS * MM + 255) / 256, 256>>>();
    corr_kernel<<<dim3(NDY * NSTRIP, NITEMS), NTHR, smem_bytes>>>();
    int total = NITEMS * 18 * HH * WW;
    epilogue_kernel<<<(total + 255) / 256, 256>>>((float*)d_out);
}

// round 12
// speedup vs baseline: 1.6315x; 1.6315x over previous
#include <cuda_runtime.h>
#include <cuda_fp16.h>
#include <cfloat>
#include <cstdint>

// Problem constants
#define NITEMS 2
#define CCH 64
#define HH 96
#define WW 96
#define HP 94
#define WP 94
#define MM (HP*WP)          // 8836 patches per item
#define SY 24               // patch rows per strip block
#define NSTRIP 4
#define NDY 187             // Dy in [-93, 93]
#define VST 97              // Vp plane row stride (floats), odd -> low conflicts
#define NTHR 768            // 24 warps
#define XH 136              // halves per x-row in smem (128 data + 8 pad = 272B)
#define SLABH (WW*XH)       // 13056 halves per slab (26112B)
#define GROWH (WW*128)      // 12288 halves per row slab in gmem (hi64|lo64 per x)

// Static device scratch (allocation-free rule)
__device__ __half g_featp[2][NITEMS][HH][GROWH];          // [t][n][row][x: hi(64)|lo(64)]
__device__ unsigned long long g_best64[NITEMS][MM];       // packed (value, ~r)

__device__ __forceinline__ unsigned su(const void* p) {
    return (unsigned)__cvta_generic_to_shared(p);
}

__device__ __forceinline__ unsigned long long packkey(float v, int r) {
    unsigned u = __float_as_uint(v);
    u = (u & 0x80000000u) ? ~u : (u | 0x80000000u);   // monotone float -> uint
    return ((unsigned long long)u << 32) | (unsigned)(~r);  // bigger = better; tie -> smaller r
}

__device__ __forceinline__ void ldsm4(uint32_t& r0, uint32_t& r1, uint32_t& r2, uint32_t& r3,
                                      unsigned a) {
    asm volatile("ldmatrix.sync.aligned.m8n8.x4.shared.b16 {%0,%1,%2,%3}, [%4];"
        : "=r"(r0), "=r"(r1), "=r"(r2), "=r"(r3) : "r"(a));
}
__device__ __forceinline__ void ldsm2(uint32_t& r0, uint32_t& r1, unsigned a) {
    asm volatile("ldmatrix.sync.aligned.m8n8.x2.shared.b16 {%0,%1}, [%2];"
        : "=r"(r0), "=r"(r1) : "r"(a));
}
__device__ __forceinline__ void mma16(float* c, uint32_t a0, uint32_t a1, uint32_t a2, uint32_t a3,
                                      uint32_t b0, uint32_t b1) {
    asm volatile("mma.sync.aligned.m16n8k16.row.col.f32.f16.f16.f32 "
        "{%0,%1,%2,%3}, {%4,%5,%6,%7}, {%8,%9}, {%0,%1,%2,%3};"
        : "+f"(c[0]), "+f"(c[1]), "+f"(c[2]), "+f"(c[3])
        : "r"(a0), "r"(a1), "r"(a2), "r"(a3), "r"(b0), "r"(b1));
}

// ---------------------------------------------------------------------------
// Kernel 1: per-pixel channel L2 normalization, fp32 NCHW -> fp16 hi/lo split
// Row slab layout: per x, 64 hi halves then 64 lo halves (256B per x).
// ---------------------------------------------------------------------------
__global__ void normalize_kernel(const float* __restrict__ f1,
                                 const float* __restrict__ f2) {
    __shared__ float tile[CCH][WW + 1];
    __shared__ float scale[WW];
    int row = blockIdx.x, t = blockIdx.y, n = blockIdx.z;
    const float* src = (t == 0 ? f1 : f2) + (size_t)n * CCH * HH * WW + (size_t)row * WW;

    for (int j = threadIdx.x; j < CCH * WW; j += 256) {
        int c = j / WW, x = j % WW;
        tile[c][x] = src[(size_t)c * HH * WW + x];
    }
    __syncthreads();
    if (threadIdx.x < WW) {
        float ss = 0.f;
        #pragma unroll
        for (int c = 0; c < CCH; c++) { float v = tile[c][threadIdx.x]; ss += v * v; }
        scale[threadIdx.x] = 1.0f / fmaxf(sqrtf(ss), 1e-12f);
    }
    __syncthreads();
    __half* dst = g_featp[t][n][row];
    for (int j = threadIdx.x; j < CCH * WW; j += 256) {
        int x = j >> 6, c = j & 63;
        float v = tile[c][x] * scale[x];
        __half hi = __float2half_rn(v);
        __half lo = __float2half_rn(v - __half2float(hi));
        dst[x * 128 + c] = hi;
        dst[x * 128 + 64 + c] = lo;
    }
}

// ---------------------------------------------------------------------------
// Kernel 2: reset argmax state (required every graph replay)
// ---------------------------------------------------------------------------
__global__ void init_kernel() {
    int i = blockIdx.x * 256 + threadIdx.x;
    if (i < NITEMS * MM) ((unsigned long long*)g_best64)[i] = 0ull;
}

// ---------------------------------------------------------------------------
// Kernel 3: displacement-decomposed correlation + argmax, 768 threads.
// Rowdot GEMM (96x96x64) on tensor cores: fp16 hi/lo 3-pass (hh + hl + lh),
// fp32 accumulate -- identical error profile to the validated 3xTF32 path.
// 24 warps: warp w -> m-tile (w%6)*16, n-cols (w/6)*24 (3 m16n8 tiles).
// Vertical running sums live in accumulator-fragment-aligned registers.
// ---------------------------------------------------------------------------
__device__ __forceinline__ void load_rows(const __half* fa, const __half* fb,
                                          __half* da, __half* db, int tid) {
    // 1536 16B-chunks per slab, 2 slabs = 3072 chunks over 768 threads.
    #pragma unroll
    for (int q = 0; q < 4; q++) {
        int idx = tid + NTHR * q;
        int tsel = idx >= 1536;
        int g = idx - 1536 * tsel;
        int x = g >> 4, seg = g & 15;
        const __half* sp = (tsel ? fb : fa) + g * 8;
        __half* dp = (tsel ? db : da) + x * XH + seg * 8;
        unsigned d = su(dp);
        asm volatile("cp.async.cg.shared.global [%0], [%1], 16;\n" :: "r"(d), "l"(sp));
    }
    asm volatile("cp.async.commit_group;\n" ::: "memory");
}

__global__ __launch_bounds__(NTHR, 1)
void corr_kernel() {
    extern __shared__ __align__(16) char smraw[];
    __half* smH = (__half*)smraw;                       // 4 slabs: [buf][A,B]
    float* Vp = (float*)(smraw + 4 * SLABH * 2);        // 96*VST floats

    const int d = blockIdx.x >> 2;         // 0..186
    const int s = blockIdx.x & 3;
    const int Dy = d - 93;
    const int item = blockIdx.y;
    const int ylo = Dy < 0 ? -Dy : 0;
    const int yhi = HP - (Dy > 0 ? Dy : 0);
    const int y0 = ylo + s * SY;
    if (y0 >= yhi) return;
    int rows = yhi - y0; if (rows > SY) rows = SY;

    const int tid = threadIdx.x;
    const int lane = tid & 31;
    const int w = tid >> 5;                // 0..23
    const int m0 = (w % 6) * 16;           // m-tile base (x)
    const int nb = (w / 6) * 24;           // n base (xr), 3 tiles of 8

    const __half* finBase  = g_featp[0][item][0];
    const __half* frefBase = g_featp[1][item][0];

    // ldmatrix per-lane byte offsets (within a slab)
    const int lm = lane >> 3, lr = lane & 7;
    const int aOff = ((m0 + lr + 8 * (lm & 1)) * XH + 8 * (lm >> 1)) * 2;   // A: 4 mats
    const int bOffBase = ((nb + lr) * XH) * 2;                               // B tile stride added later
    const int bK = ((lm & 1) * 8) * 2;                                       // x2: k-half select

    float acc[3][4], S1[3][4], S2[3][4];
    #pragma unroll
    for (int t = 0; t < 3; t++)
        #pragma unroll
        for (int p = 0; p < 4; p++) { S1[t][p] = 0.f; S2[t][p] = 0.f; }

    load_rows(finBase + (size_t)y0 * GROWH, frefBase + (size_t)(y0 + Dy) * GROWH,
              smH, smH + SLABH, tid);

    for (int k = 0; k < rows + 2; k++) {
        const int buf = k & 1;
        asm volatile("cp.async.wait_group 0;\n" ::: "memory");
        __syncthreads();
        if (k + 1 < rows + 2) {
            int p = y0 + k + 1;
            load_rows(finBase + (size_t)p * GROWH, frefBase + (size_t)(p + Dy) * GROWH,
                      smH + (buf ^ 1) * 2 * SLABH, smH + (buf ^ 1) * 2 * SLABH + SLABH, tid);
        }

        const __half* As = smH + buf * 2 * SLABH;
        const __half* Bs = As + SLABH;

        #pragma unroll
        for (int t = 0; t < 3; t++)
            #pragma unroll
            for (int p = 0; p < 4; p++) acc[t][p] = 0.f;

        // ---- rowdot GEMM: 4 ksteps of 16 channels ----
        #pragma unroll
        for (int ks = 0; ks < 4; ks++) {
            uint32_t ah0, ah1, ah2, ah3, al0, al1, al2, al3;
            unsigned abase = su((const char*)As + aOff + ks * 32);
            ldsm4(ah0, ah1, ah2, ah3, abase);
            ldsm4(al0, al1, al2, al3, abase + 128);
            #pragma unroll
            for (int t = 0; t < 3; t++) {
                uint32_t bh0, bh1, bl0, bl1;
                unsigned bbase = su((const char*)Bs + bOffBase + t * (8 * XH * 2) + bK + ks * 32);
                ldsm2(bh0, bh1, bbase);
                ldsm2(bl0, bl1, bbase + 128);
                mma16(acc[t], ah0, ah1, ah2, ah3, bh0, bh1);   // hi*hi
                mma16(acc[t], ah0, ah1, ah2, ah3, bl0, bl1);   // hi*lo
                mma16(acc[t], al0, al1, al2, al3, bh0, bh1);   // lo*hi
            }
        }

        // ---- vertical running sums in regs; V -> smem when emitting ----
        const bool emit = (k >= 2);
        #pragma unroll
        for (int t = 0; t < 3; t++) {
            #pragma unroll
            for (int p = 0; p < 4; p++) {
                float rd = acc[t][p];
                if (emit) {
                    int row = m0 + (lane >> 2) + 8 * (p >> 1);
                    int col = nb + t * 8 + (lane & 3) * 2 + (p & 1);
                    Vp[row * VST + col] = S2[t][p] + rd;
                }
                S2[t][p] = S1[t][p] + rd;
                S1[t][p] = rd;
            }
        }

        // ---- horizontal 3-diag sum + argmax over rx, merged via atomicMax ----
        if (emit) {
            __syncthreads();
            const int y = y0 + k - 2;
            const int ry = y + Dy;
            #pragma unroll
            for (int i = 0; i < 4; i++) {
                int xx = w + 24 * i;
                float bv = -FLT_MAX; int brx = 0;
                if (xx < HP) {
                    const float* v0 = Vp + xx * VST;
                    #pragma unroll
                    for (int j = 0; j < 3; j++) {
                        int rx = lane + 32 * j;
                        if (rx < HP) {
                            float v = v0[rx] + v0[VST + 1 + rx] + v0[2 * VST + 2 + rx];
                            if (v > bv) { bv = v; brx = rx; }
                        }
                    }
                }
                #pragma unroll
                for (int off = 16; off >= 1; off >>= 1) {
                    float ov = __shfl_down_sync(0xffffffffu, bv, off);
                    int orx = __shfl_down_sync(0xffffffffu, brx, off);
                    if (ov > bv || (ov == bv && orx < brx)) { bv = ov; brx = orx; }
                }
                if (lane == 0 && xx < HP) {
                    atomicMax(&g_best64[item][y * WP + xx], packkey(bv, ry * WP + brx));
                }
            }
        }
    }
}

// ---------------------------------------------------------------------------
// Kernel 4: decode best index -> flow -> shift -> reorder. out (N,18,H,W) f32
// ---------------------------------------------------------------------------
__global__ void epilogue_kernel(float* __restrict__ out) {
    int i = blockIdx.x * 256 + threadIdx.x;
    const int total = NITEMS * 18 * HH * WW;
    if (i >= total) return;
    int w = i % WW;
    int h = (i / WW) % HH;
    int ch = (i / (WW * HH)) % 18;
    int n = i / (WW * HH * 18);
    int s = ch >> 1, comp = ch & 1;
    int si = s / 3, sj = s % 3;
    int y = h - si, x = w - sj;
    float val = 0.f;
    if (y >= 0 && y < HP && x >= 0 && x < WP) {
        unsigned long long key = g_best64[n][y * WP + x];
        int idx = (int)(~(unsigned)(key & 0xffffffffull));
        val = (comp == 0) ? (float)(idx / WP - y) : (float)(idx % WP - x);
    }
    out[i] = val;
}

// ---------------------------------------------------------------------------
extern "C" void kernel_launch(void* const* d_in, const int* in_sizes, int n_in,
                              void* d_out, int out_size) {
    const float* f1 = (const float*)d_in[0];
    const float* f2 = (const float*)d_in[1];

    const int smem_bytes = 4 * SLABH * 2 + HH * VST * 4;   // 104448 + 37248 = 141696
    cudaFuncSetAttribute(corr_kernel,
                         cudaFuncAttributeMaxDynamicSharedMemorySize, smem_bytes);

    normalize_kernel<<<dim3(HH, 2, NITEMS), 256>>>(f1, f2);
    init_kernel<<<(NITEMS * MM + 255) / 256, 256>>>();
    corr_kernel<<<dim3(NDY * NSTRIP, NITEMS), NTHR, smem_bytes>>>();
    int total = NITEMS * 18 * HH * WW;
    epilogue_kernel<<<(total + 255) / 256, 256>>>((float*)d_out);
}

// round 13
// speedup vs baseline: 1.7964x; 1.1010x over previous
#include <cuda_runtime.h>
#include <cuda_fp16.h>
#include <cfloat>
#include <cstdint>

// Problem constants
#define NITEMS 2
#define CCH 64
#define HH 96
#define WW 96
#define HP 94
#define WP 94
#define MM (HP*WP)          // 8836 patches per item
#define SY 24               // patch rows per strip block
#define NSTRIP 4
#define NDY 187             // Dy in [-93, 93]
#define VST 100             // Vp plane row stride (floats): deg-2 STS.64 banks
#define PLANE (HH*VST)      // 9600 floats per V plane
#define NTHR 768            // 24 warps
#define XH 136              // halves per x-row in smem (128 data + 8 pad = 272B)
#define SLABH (WW*XH)       // 13056 halves per slab (26112B)
#define GROWH (WW*128)      // 12288 halves per row slab in gmem (hi64|lo64 per x)

// Static device scratch (allocation-free rule)
__device__ __half g_featp[2][NITEMS][HH][GROWH];          // [t][n][row][x: hi(64)|lo(64)]
__device__ unsigned long long g_best64[NITEMS][MM];       // packed (value, ~r)

__device__ __forceinline__ unsigned su(const void* p) {
    return (unsigned)__cvta_generic_to_shared(p);
}

__device__ __forceinline__ unsigned long long packkey(float v, int r) {
    unsigned u = __float_as_uint(v);
    u = (u & 0x80000000u) ? ~u : (u | 0x80000000u);   // monotone float -> uint
    return ((unsigned long long)u << 32) | (unsigned)(~r);  // bigger = better; tie -> smaller r
}

__device__ __forceinline__ void ldsm4(uint32_t& r0, uint32_t& r1, uint32_t& r2, uint32_t& r3,
                                      unsigned a) {
    asm volatile("ldmatrix.sync.aligned.m8n8.x4.shared.b16 {%0,%1,%2,%3}, [%4];"
        : "=r"(r0), "=r"(r1), "=r"(r2), "=r"(r3) : "r"(a));
}
__device__ __forceinline__ void ldsm2(uint32_t& r0, uint32_t& r1, unsigned a) {
    asm volatile("ldmatrix.sync.aligned.m8n8.x2.shared.b16 {%0,%1}, [%2];"
        : "=r"(r0), "=r"(r1) : "r"(a));
}
__device__ __forceinline__ void mma16(float* c, uint32_t a0, uint32_t a1, uint32_t a2, uint32_t a3,
                                      uint32_t b0, uint32_t b1) {
    asm volatile("mma.sync.aligned.m16n8k16.row.col.f32.f16.f16.f32 "
        "{%0,%1,%2,%3}, {%4,%5,%6,%7}, {%8,%9}, {%0,%1,%2,%3};"
        : "+f"(c[0]), "+f"(c[1]), "+f"(c[2]), "+f"(c[3])
        : "r"(a0), "r"(a1), "r"(a2), "r"(a3), "r"(b0), "r"(b1));
}

// ---------------------------------------------------------------------------
// Kernel 1: per-pixel channel L2 normalization, fp32 NCHW -> fp16 hi/lo split
// Row slab layout: per x, 64 hi halves then 64 lo halves (256B per x).
// ---------------------------------------------------------------------------
__global__ void normalize_kernel(const float* __restrict__ f1,
                                 const float* __restrict__ f2) {
    __shared__ float tile[CCH][WW + 1];
    __shared__ float scale[WW];
    int row = blockIdx.x, t = blockIdx.y, n = blockIdx.z;
    const float* src = (t == 0 ? f1 : f2) + (size_t)n * CCH * HH * WW + (size_t)row * WW;

    for (int j = threadIdx.x; j < CCH * WW; j += 256) {
        int c = j / WW, x = j % WW;
        tile[c][x] = src[(size_t)c * HH * WW + x];
    }
    __syncthreads();
    if (threadIdx.x < WW) {
        float ss = 0.f;
        #pragma unroll
        for (int c = 0; c < CCH; c++) { float v = tile[c][threadIdx.x]; ss += v * v; }
        scale[threadIdx.x] = 1.0f / fmaxf(sqrtf(ss), 1e-12f);
    }
    __syncthreads();
    __half* dst = g_featp[t][n][row];
    for (int j = threadIdx.x; j < CCH * WW; j += 256) {
        int x = j >> 6, c = j & 63;
        float v = tile[c][x] * scale[x];
        __half hi = __float2half_rn(v);
        __half lo = __float2half_rn(v - __half2float(hi));
        dst[x * 128 + c] = hi;
        dst[x * 128 + 64 + c] = lo;
    }
}

// ---------------------------------------------------------------------------
// Kernel 2: reset argmax state (required every graph replay)
// ---------------------------------------------------------------------------
__global__ void init_kernel() {
    int i = blockIdx.x * 256 + threadIdx.x;
    if (i < NITEMS * MM) ((unsigned long long*)g_best64)[i] = 0ull;
}

// ---------------------------------------------------------------------------
// Kernel 3: displacement-decomposed correlation + argmax, 768 threads.
// Software-pipelined: at iter k -- GEMM row k (tensor), emit V(row k-2) into
// plane[k&1] (STS.64, deg-2 banks), argmax V(row k-3) from plane[(k&1)^1].
// One __syncthreads per iteration covers slab swap + plane handoff; across
// the 6 warps/SMSP the argmax ALU/LDS work overlaps the tensor-pipe waits.
// ---------------------------------------------------------------------------
__device__ __forceinline__ void load_rows(const __half* fa, const __half* fb,
                                          __half* da, __half* db, int tid) {
    #pragma unroll
    for (int q = 0; q < 4; q++) {
        int idx = tid + NTHR * q;
        int tsel = idx >= 1536;
        int g = idx - 1536 * tsel;
        int x = g >> 4, seg = g & 15;
        const __half* sp = (tsel ? fb : fa) + g * 8;
        __half* dp = (tsel ? db : da) + x * XH + seg * 8;
        unsigned d = su(dp);
        asm volatile("cp.async.cg.shared.global [%0], [%1], 16;\n" :: "r"(d), "l"(sp));
    }
    asm volatile("cp.async.commit_group;\n" ::: "memory");
}

__global__ __launch_bounds__(NTHR, 1)
void corr_kernel() {
    extern __shared__ __align__(16) char smraw[];
    __half* smH = (__half*)smraw;                       // 4 slabs: [buf][A,B]
    float* VpBase = (float*)(smraw + 4 * SLABH * 2);    // 2 planes of PLANE floats

    const int d = blockIdx.x >> 2;         // 0..186
    const int s = blockIdx.x & 3;
    const int Dy = d - 93;
    const int item = blockIdx.y;
    const int ylo = Dy < 0 ? -Dy : 0;
    const int yhi = HP - (Dy > 0 ? Dy : 0);
    const int y0 = ylo + s * SY;
    if (y0 >= yhi) return;
    int rows = yhi - y0; if (rows > SY) rows = SY;

    const int tid = threadIdx.x;
    const int lane = tid & 31;
    const int w = tid >> 5;                // 0..23
    const int m0 = (w % 6) * 16;           // m-tile base (x)
    const int nb = (w / 6) * 24;           // n base (xr), 3 tiles of 8

    const __half* finBase  = g_featp[0][item][0];
    const __half* frefBase = g_featp[1][item][0];

    // ldmatrix per-lane byte offsets (within a slab)
    const int lm = lane >> 3, lr = lane & 7;
    const int aOff = ((m0 + lr + 8 * (lm & 1)) * XH + 8 * (lm >> 1)) * 2;   // A: 4 mats
    const int bOffBase = ((nb + lr) * XH) * 2;
    const int bK = ((lm & 1) * 8) * 2;

    // emit addressing (fragment -> plane), col even -> 8B-aligned float2
    const int eRow = m0 + (lane >> 2);
    const int eCol = nb + (lane & 3) * 2;

    float acc[3][4], S1[3][4], S2[3][4];
    #pragma unroll
    for (int t = 0; t < 3; t++)
        #pragma unroll
        for (int p = 0; p < 4; p++) { S1[t][p] = 0.f; S2[t][p] = 0.f; }

    load_rows(finBase + (size_t)y0 * GROWH, frefBase + (size_t)(y0 + Dy) * GROWH,
              smH, smH + SLABH, tid);

    for (int k = 0; k < rows + 3; k++) {
        const int buf = k & 1;
        asm volatile("cp.async.wait_group 0;\n" ::: "memory");
        __syncthreads();   // slab ready + Vp plane handoff
        if (k + 1 < rows + 2) {
            int p = y0 + k + 1;
            load_rows(finBase + (size_t)p * GROWH, frefBase + (size_t)(p + Dy) * GROWH,
                      smH + (buf ^ 1) * 2 * SLABH, smH + (buf ^ 1) * 2 * SLABH + SLABH, tid);
        }

        if (k < rows + 2) {
            const __half* As = smH + buf * 2 * SLABH;
            const __half* Bs = As + SLABH;

            #pragma unroll
            for (int t = 0; t < 3; t++)
                #pragma unroll
                for (int p = 0; p < 4; p++) acc[t][p] = 0.f;

            // ---- rowdot GEMM: 4 ksteps of 16 channels, fp16 hi/lo 3-pass ----
            #pragma unroll
            for (int ks = 0; ks < 4; ks++) {
                uint32_t ah0, ah1, ah2, ah3, al0, al1, al2, al3;
                unsigned abase = su((const char*)As + aOff + ks * 32);
                ldsm4(ah0, ah1, ah2, ah3, abase);
                ldsm4(al0, al1, al2, al3, abase + 128);
                #pragma unroll
                for (int t = 0; t < 3; t++) {
                    uint32_t bh0, bh1, bl0, bl1;
                    unsigned bbase = su((const char*)Bs + bOffBase + t * (8 * XH * 2) + bK + ks * 32);
                    ldsm2(bh0, bh1, bbase);
                    ldsm2(bl0, bl1, bbase + 128);
                    mma16(acc[t], ah0, ah1, ah2, ah3, bh0, bh1);   // hi*hi
                    mma16(acc[t], ah0, ah1, ah2, ah3, bl0, bl1);   // hi*lo
                    mma16(acc[t], al0, al1, al2, al3, bh0, bh1);   // lo*hi
                }
            }

            // ---- vertical running sums in regs; V -> plane[k&1] via STS.64 ----
            const bool emit = (k >= 2);
            float* plane = VpBase + buf * PLANE;
            #pragma unroll
            for (int t = 0; t < 3; t++) {
                #pragma unroll
                for (int ph = 0; ph < 2; ph++) {
                    float r0 = acc[t][2 * ph], r1 = acc[t][2 * ph + 1];
                    if (emit) {
                        float2 e = make_float2(S2[t][2 * ph] + r0, S2[t][2 * ph + 1] + r1);
                        *(float2*)(plane + (eRow + 8 * ph) * VST + eCol + t * 8) = e;
                    }
                    S2[t][2 * ph]     = S1[t][2 * ph]     + r0;
                    S2[t][2 * ph + 1] = S1[t][2 * ph + 1] + r1;
                    S1[t][2 * ph]     = r0;
                    S1[t][2 * ph + 1] = r1;
                }
            }
        }

        // ---- argmax over V(row y0+k-3) from plane[(k&1)^1] ----
        if (k >= 3) {
            const float* plane = VpBase + (buf ^ 1) * PLANE;
            const int y = y0 + k - 3;
            const int ry = y + Dy;
            #pragma unroll
            for (int i = 0; i < 4; i++) {
                int xx = w + 24 * i;
                float bv = -FLT_MAX; int brx = 0;
                if (xx < HP) {
                    const float* v0 = plane + xx * VST;
                    #pragma unroll
                    for (int j = 0; j < 3; j++) {
                        int rx = lane + 32 * j;
                        if (rx < HP) {
                            float v = v0[rx] + v0[VST + 1 + rx] + v0[2 * VST + 2 + rx];
                            if (v > bv) { bv = v; brx = rx; }
                        }
                    }
                }
                #pragma unroll
                for (int off = 16; off >= 1; off >>= 1) {
                    float ov = __shfl_down_sync(0xffffffffu, bv, off);
                    int orx = __shfl_down_sync(0xffffffffu, brx, off);
                    if (ov > bv || (ov == bv && orx < brx)) { bv = ov; brx = orx; }
                }
                if (lane == 0 && xx < HP) {
                    atomicMax(&g_best64[item][y * WP + xx], packkey(bv, ry * WP + brx));
                }
            }
        }
    }
}

// ---------------------------------------------------------------------------
// Kernel 4: decode best index -> flow -> shift -> reorder. out (N,18,H,W) f32
// ---------------------------------------------------------------------------
__global__ void epilogue_kernel(float* __restrict__ out) {
    int i = blockIdx.x * 256 + threadIdx.x;
    const int total = NITEMS * 18 * HH * WW;
    if (i >= total) return;
    int w = i % WW;
    int h = (i / WW) % HH;
    int ch = (i / (WW * HH)) % 18;
    int n = i / (WW * HH * 18);
    int s = ch >> 1, comp = ch & 1;
    int si = s / 3, sj = s % 3;
    int y = h - si, x = w - sj;
    float val = 0.f;
    if (y >= 0 && y < HP && x >= 0 && x < WP) {
        unsigned long long key = g_best64[n][y * WP + x];
        int idx = (int)(~(unsigned)(key & 0xffffffffull));
        val = (comp == 0) ? (float)(idx / WP - y) : (float)(idx % WP - x);
    }
    out[i] = val;
}

// ---------------------------------------------------------------------------
extern "C" void kernel_launch(void* const* d_in, const int* in_sizes, int n_in,
                              void* d_out, int out_size) {
    const float* f1 = (const float*)d_in[0];
    const float* f2 = (const float*)d_in[1];

    const int smem_bytes = 4 * SLABH * 2 + 2 * PLANE * 4;   // 104448 + 76800 = 181248
    cudaFuncSetAttribute(corr_kernel,
                         cudaFuncAttributeMaxDynamicSharedMemorySize, smem_bytes);

    normalize_kernel<<<dim3(HH, 2, NITEMS), 256>>>(f1, f2);
    init_kernel<<<(NITEMS * MM + 255) / 256, 256>>>();
    corr_kernel<<<dim3(NDY * NSTRIP, NITEMS), NTHR, smem_bytes>>>();
    int total = NITEMS * 18 * HH * WW;
    epilogue_kernel<<<(total + 255) / 256, 256>>>((float*)d_out);
}